// round 3
// baseline (speedup 1.0000x reference)
#include <cuda_runtime.h>
#include <cuda_bf16.h>
#include <math_constants.h>

#define BB 32
#define DD 256
#define TT 1024
#define KK 8192
#define NN (BB * TT)
#define ZQ_ELEMS (BB * DD * TT)

#define CAP 128
#define MARGIN 2.0e-3f

__device__ float  g_e2[KK];
__device__ float  g_t1[NN];
__device__ int    g_idx[NN];
__device__ double g_loss;
__device__ unsigned short g_xbf[NN * DD];        // bf16 bits, row-major [n][d]
__device__ float          g_xf [NN * DD];        // fp32 row-major [n][d]
__device__ unsigned short g_ebf[KK * DD];        // bf16 bits, row-major [k][d]
__device__ unsigned long long g_cand[(size_t)NN * CAP];  // (score_bits<<32)|k
__device__ int    g_ccnt[NN];
__device__ int    g_runbits[NN];

// ---------------- helpers ----------------
__device__ __forceinline__ unsigned smem_u32(const void* p) {
    unsigned a;
    asm("{ .reg .u64 t; cvta.to.shared.u64 t, %1; cvt.u32.u64 %0, t; }" : "=r"(a) : "l"(p));
    return a;
}
__device__ __forceinline__ void cp16(unsigned dst, const void* src) {
    asm volatile("cp.async.cg.shared.global [%0], [%1], 16;" :: "r"(dst), "l"(src));
}
#define CP_COMMIT() asm volatile("cp.async.commit_group;")
#define CP_WAIT0()  asm volatile("cp.async.wait_group 0;")

__device__ __forceinline__ void ldsm4(unsigned r[4], unsigned addr) {
    asm volatile("ldmatrix.sync.aligned.m8n8.x4.shared.b16 {%0,%1,%2,%3}, [%4];"
                 : "=r"(r[0]), "=r"(r[1]), "=r"(r[2]), "=r"(r[3]) : "r"(addr));
}
__device__ __forceinline__ void mma16816(float c[4], const unsigned a[4], unsigned b0, unsigned b1) {
    asm volatile("mma.sync.aligned.m16n8k16.row.col.f32.bf16.bf16.f32 "
                 "{%0,%1,%2,%3},{%4,%5,%6,%7},{%8,%9},{%0,%1,%2,%3};"
                 : "+f"(c[0]), "+f"(c[1]), "+f"(c[2]), "+f"(c[3])
                 : "r"(a[0]), "r"(a[1]), "r"(a[2]), "r"(a[3]), "r"(b0), "r"(b1));
}
__device__ __forceinline__ unsigned pack_bf2(float a, float b) {
    __nv_bfloat162 h = __floats2bfloat162_rn(a, b);
    return *reinterpret_cast<unsigned*>(&h);
}
// exact sequential-FMA dot over d=0..255 (bit-matches round-1 pipeline)
__device__ __forceinline__ float exact_dist(int n, int k, const float* __restrict__ emb) {
    const float4* xp = (const float4*)(g_xf + (size_t)n * DD);
    const float4* ep = (const float4*)(emb + (size_t)k * DD);
    float dot = 0.f;
#pragma unroll 8
    for (int i = 0; i < 64; i++) {
        float4 xv = xp[i], ev = ep[i];
        dot = __fmaf_rn(xv.x, ev.x, dot);
        dot = __fmaf_rn(xv.y, ev.y, dot);
        dot = __fmaf_rn(xv.z, ev.z, dot);
        dot = __fmaf_rn(xv.w, ev.w, dot);
    }
    return __fsub_rn(__fadd_rn(g_t1[n], g_e2[k]), __fmul_rn(2.0f, dot));
}

// ---------------- prep kernels ----------------
__global__ void prep_e2(const float* __restrict__ emb) {
    int k = blockIdx.x * 8 + (threadIdx.x >> 5);
    int lane = threadIdx.x & 31;
    const float* row = emb + (size_t)k * DD;
    float s = 0.f;
#pragma unroll
    for (int j = 0; j < 8; j++) { float v = row[lane + 32 * j]; s = __fmaf_rn(v, v, s); }
#pragma unroll
    for (int o = 16; o > 0; o >>= 1) s += __shfl_xor_sync(0xffffffffu, s, o);
    if (lane == 0) g_e2[k] = s;
    if (blockIdx.x == 0 && threadIdx.x == 0) g_loss = 0.0;
}

__global__ void prep_t1(const float* __restrict__ ze) {
    int n = blockIdx.x * 256 + threadIdx.x;
    int b = n >> 10, t = n & 1023;
    const float* p = ze + ((size_t)b * DD) * TT + t;
    float acc = 0.f;
    for (int d = 0; d < DD; d++) {
        float v = p[(size_t)d * TT];
        acc = __fadd_rn(acc, __fmul_rn(v, v));
    }
    g_t1[n] = acc;
}

__global__ void prep_ebf(const float* __restrict__ emb) {
    int i = blockIdx.x * 256 + threadIdx.x;   // float4 index
    float4 v = ((const float4*)emb)[i];
    uint2 o;
    o.x = pack_bf2(v.x, v.y);
    o.y = pack_bf2(v.z, v.w);
    ((uint2*)g_ebf)[i] = o;
}

// transpose z_e [b][d][t] -> g_xf/g_xbf row-major [n][d]
__global__ void prep_x(const float* __restrict__ ze) {
    __shared__ float sm[32 * 257];
    int n0 = blockIdx.x * 32;
    int b = n0 >> 10, t0 = n0 & 1023;
    int tid = threadIdx.x, w = tid >> 5, l = tid & 31;
#pragma unroll
    for (int j = 0; j < 32; j++) {
        int d = w * 32 + j;
        sm[l * 257 + d] = ze[((size_t)b * DD + d) * TT + t0 + l];
    }
    __syncthreads();
    int r = tid >> 3, c = tid & 7;
    float4* xo = (float4*)(g_xf + (size_t)(n0 + r) * DD);
    uint2*  bo = (uint2*)(g_xbf + (size_t)(n0 + r) * DD);
#pragma unroll
    for (int j = 0; j < 8; j++) {
        int ch = c + j * 8;
        float4 v;
        v.x = sm[r * 257 + ch * 4 + 0];
        v.y = sm[r * 257 + ch * 4 + 1];
        v.z = sm[r * 257 + ch * 4 + 2];
        v.w = sm[r * 257 + ch * 4 + 3];
        xo[ch] = v;
        uint2 o; o.x = pack_bf2(v.x, v.y); o.y = pack_bf2(v.z, v.w);
        bo[ch] = o;
    }
}

// ---------------- main MMA scan ----------------
// grid 256 CTAs x 256 thr. smem: A[128][256]bf16 sw + 2x E[128][256]bf16 sw = 192KB
#define AS_BYTES 65536
#define ES_BYTES 65536
extern __shared__ unsigned char smem_mma[];

__global__ __launch_bounds__(256, 1) void vq_mma() {
    __shared__ int runmin_s[128];
    __shared__ int cnt_s[128];
    const int tid = threadIdx.x, wid = tid >> 5, lane = tid & 31;
    const int wm = wid & 3, wn = wid >> 2;
    const int n0 = blockIdx.x * 128;

    unsigned As = smem_u32(smem_mma);
    unsigned Es0 = As + AS_BYTES;

    if (tid < 128) { runmin_s[tid] = 0x7F800000; cnt_s[tid] = 0; }

    // load A (whole 128 rows x 256 d, bf16, swizzled 16B pieces)
#pragma unroll
    for (int t = 0; t < 16; t++) {
        int i = tid + t * 256;                 // piece id, 4096 total
        int row = i >> 5, p = i & 31;
        cp16(As + row * 512 + ((p ^ (row & 7)) << 4),
             g_xbf + (size_t)(n0 + row) * DD + p * 8);
    }
    // load E tile 0 into buf 0
#pragma unroll
    for (int t = 0; t < 16; t++) {
        int i = tid + t * 256;
        int row = i >> 5, p = i & 31;
        cp16(Es0 + row * 512 + ((p ^ (row & 7)) << 4),
             g_ebf + (size_t)row * DD + p * 8);
    }
    CP_COMMIT();
    CP_WAIT0();
    __syncthreads();

    // t1 for this thread's rows
    const int g = lane >> 2;
    float t1v[2][2];
#pragma unroll
    for (int mf = 0; mf < 2; mf++) {
        t1v[mf][0] = g_t1[n0 + wm * 32 + mf * 16 + g];
        t1v[mf][1] = g_t1[n0 + wm * 32 + mf * 16 + g + 8];
    }

    // precomputed ldmatrix row bases
    int rowA[2], rowB[4];
#pragma unroll
    for (int mf = 0; mf < 2; mf++) rowA[mf] = wm * 32 + mf * 16 + (lane & 15);
    {
        int q = lane >> 3;
#pragma unroll
        for (int nf2 = 0; nf2 < 4; nf2++)
            rowB[nf2] = wn * 64 + nf2 * 16 + ((q >> 1) << 3) + (lane & 7);
    }
    const int pA = (lane >> 4);      // extra piece offset for A
    const int pB = (lane >> 3) & 1;  // extra piece offset for B

    int buf = 0;
    for (int kt_i = 0; kt_i < 64; kt_i++) {
        unsigned EsC = Es0 + buf * ES_BYTES;
        // prefetch next E tile into other buffer
        if (kt_i + 1 < 64) {
            unsigned EsN = Es0 + (buf ^ 1) * ES_BYTES;
            const unsigned short* src = g_ebf + (size_t)(kt_i + 1) * 128 * DD;
#pragma unroll
            for (int t = 0; t < 16; t++) {
                int i = tid + t * 256;
                int row = i >> 5, p = i & 31;
                cp16(EsN + row * 512 + ((p ^ (row & 7)) << 4), src + (size_t)row * DD + p * 8);
            }
            CP_COMMIT();
        }

        float acc[2][8][4];
#pragma unroll
        for (int mf = 0; mf < 2; mf++)
#pragma unroll
            for (int nf = 0; nf < 8; nf++)
#pragma unroll
                for (int r = 0; r < 4; r++) acc[mf][nf][r] = 0.f;

#pragma unroll
        for (int ks = 0; ks < 16; ks++) {
            unsigned aF[2][4], bF[4][4];
#pragma unroll
            for (int mf = 0; mf < 2; mf++) {
                int row = rowA[mf], p = 2 * ks + pA;
                ldsm4(aF[mf], As + row * 512 + ((p ^ (row & 7)) << 4));
            }
#pragma unroll
            for (int nf2 = 0; nf2 < 4; nf2++) {
                int row = rowB[nf2], p = 2 * ks + pB;
                ldsm4(bF[nf2], EsC + row * 512 + ((p ^ (row & 7)) << 4));
            }
#pragma unroll
            for (int mf = 0; mf < 2; mf++)
#pragma unroll
                for (int nf = 0; nf < 8; nf++)
                    mma16816(acc[mf][nf], aF[mf], bF[nf >> 1][(nf & 1) * 2], bF[nf >> 1][(nf & 1) * 2 + 1]);
        }

        // epilogue: approx score, running min, candidate append
        int kt = kt_i * 128;
#pragma unroll
        for (int nf = 0; nf < 8; nf++) {
            int kb = kt + wn * 64 + nf * 8 + 2 * (lane & 3);
            float e2a = g_e2[kb], e2b = g_e2[kb + 1];
#pragma unroll
            for (int mf = 0; mf < 2; mf++) {
                int r0 = wm * 32 + mf * 16 + g;
#pragma unroll
                for (int rg = 0; rg < 4; rg++) {
                    int r = r0 + ((rg >> 1) << 3);
                    int k = kb + (rg & 1);
                    float e2v = (rg & 1) ? e2b : e2a;
                    float t1x = t1v[mf][rg >> 1];
                    float s = __fsub_rn(__fadd_rn(t1x, e2v), __fmul_rn(2.0f, acc[mf][nf][rg]));
                    int sb = __float_as_int(s);
                    int cur = runmin_s[r];
                    if (sb < cur) atomicMin(&runmin_s[r], sb);
                    if (s <= __int_as_float(cur) + MARGIN) {
                        int pos = atomicAdd(&cnt_s[r], 1);
                        if (pos < CAP)
                            g_cand[(size_t)(n0 + r) * CAP + pos] =
                                ((unsigned long long)(unsigned)sb << 32) | (unsigned)k;
                    }
                }
            }
        }

        CP_WAIT0();
        __syncthreads();
        buf ^= 1;
    }

    if (tid < 128) {
        g_runbits[n0 + tid] = runmin_s[tid];
        g_ccnt[n0 + tid] = cnt_s[tid];
    }
}

// ---------------- exact refine ----------------
__global__ void vq_refine(const float* __restrict__ emb, float* __restrict__ out) {
    int n = blockIdx.x * 256 + threadIdx.x;
    int cnt = g_ccnt[n];
    float bestv = CUDART_INF_F;
    int bestk = 0;
    if (cnt <= CAP) {
        float thr = __int_as_float(g_runbits[n]) + MARGIN;
        const unsigned long long* cl = g_cand + (size_t)n * CAP;
        for (int i = 0; i < cnt; i++) {
            unsigned long long c = cl[i];
            float s = __int_as_float((int)(c >> 32));
            if (s <= thr) {
                int k = (int)(c & 0xffffffffu);
                float dv = exact_dist(n, k, emb);
                if (dv < bestv || (dv == bestv && k < bestk)) { bestv = dv; bestk = k; }
            }
        }
    } else {
        for (int k = 0; k < KK; k++) {   // overflow fallback (provably correct, ~never)
            float dv = exact_dist(n, k, emb);
            if (dv < bestv || (dv == bestv && k < bestk)) { bestv = dv; bestk = k; }
        }
    }
    g_idx[n] = bestk;
    out[ZQ_ELEMS + 1 + n] = (float)bestk;
}

// ---------------- gather + STE + loss ----------------
__global__ void vq_gather(const float* __restrict__ ze, const float* __restrict__ emb,
                          float* __restrict__ out) {
    __shared__ float sm[32 * 257];
    __shared__ double sred[256];
    int n0 = blockIdx.x * 32;
    int b = n0 >> 10, t0 = n0 & 1023;
    int tid = threadIdx.x;
    {   // gather 32 emb rows into smem (coalesced along d)
        int r = tid >> 3, c = tid & 7;
        int k = g_idx[n0 + r];
        const float4* er = (const float4*)(emb + (size_t)k * DD);
#pragma unroll
        for (int j = 0; j < 8; j++) {
            int ch = c + j * 8;
            float4 v = er[ch];
            sm[r * 257 + ch * 4 + 0] = v.x;
            sm[r * 257 + ch * 4 + 1] = v.y;
            sm[r * 257 + ch * 4 + 2] = v.z;
            sm[r * 257 + ch * 4 + 3] = v.w;
        }
    }
    __syncthreads();
    int w = tid >> 5, l = tid & 31;
    double lsum = 0.0;
#pragma unroll
    for (int j = 0; j < 32; j++) {
        int d = w * 32 + j;
        size_t off = ((size_t)b * DD + d) * TT + t0 + l;
        float e = sm[l * 257 + d];
        float v = ze[off];
        float diff = __fsub_rn(e, v);
        out[off] = __fadd_rn(v, diff);   // STE round-trip replicated
        lsum += (double)__fmul_rn(diff, diff);
    }
    sred[tid] = lsum;
    __syncthreads();
    for (int s = 128; s > 0; s >>= 1) {
        if (tid < s) sred[tid] += sred[tid + s];
        __syncthreads();
    }
    if (tid == 0) atomicAdd(&g_loss, sred[0]);
}

__global__ void vq_finalize(float* __restrict__ out) {
    out[ZQ_ELEMS] = (float)(g_loss / (double)ZQ_ELEMS);
}

// ---------------- launch ----------------
extern "C" void kernel_launch(void* const* d_in, const int* in_sizes, int n_in,
                              void* d_out, int out_size) {
    (void)in_sizes; (void)n_in; (void)out_size;
    const float* ze = (const float*)d_in[0];
    const float* emb = (const float*)d_in[1];
    float* out = (float*)d_out;

    static int smem_set = 0;
    if (!smem_set) {
        cudaFuncSetAttribute(vq_mma, cudaFuncAttributeMaxDynamicSharedMemorySize,
                             AS_BYTES + 2 * ES_BYTES);
        smem_set = 1;
    }

    prep_e2<<<KK / 8, 256>>>(emb);
    prep_t1<<<NN / 256, 256>>>(ze);
    prep_ebf<<<(KK * DD / 4) / 256, 256>>>(emb);
    prep_x<<<NN / 32, 256>>>(ze);
    vq_mma<<<256, 256, AS_BYTES + 2 * ES_BYTES>>>();
    vq_refine<<<NN / 256, 256>>>(emb, out);
    vq_gather<<<NN / 32, 256>>>(ze, emb, out);
    vq_finalize<<<1, 1>>>(out);
}

// round 4
// speedup vs baseline: 23.1446x; 23.1446x over previous
#include <cuda_runtime.h>
#include <cuda_bf16.h>
#include <math_constants.h>

#define BB 32
#define DD 256
#define TT 1024
#define KK 8192
#define NN (BB * TT)
#define ZQ_ELEMS (BB * DD * TT)

#define CAP 256
#define MARGIN 2.0e-3f

__device__ float  g_e2[KK];
__device__ float  g_t1[NN];
__device__ int    g_idx[NN];
__device__ double g_loss;
__device__ unsigned short g_xbf[NN * DD];        // bf16 bits, row-major [n][d]
__device__ float          g_xf [NN * DD];        // fp32 row-major [n][d]
__device__ unsigned short g_ebf[KK * DD];        // bf16 bits, row-major [k][d]
__device__ unsigned long long g_cand[(size_t)NN * CAP];  // (score_bits<<32)|k
__device__ int    g_ccnt[NN];
__device__ int    g_runbits[NN];

// ---------------- helpers ----------------
__device__ __forceinline__ unsigned smem_u32(const void* p) {
    unsigned a;
    asm("{ .reg .u64 t; cvta.to.shared.u64 t, %1; cvt.u32.u64 %0, t; }" : "=r"(a) : "l"(p));
    return a;
}
__device__ __forceinline__ void cp16(unsigned dst, const void* src) {
    asm volatile("cp.async.cg.shared.global [%0], [%1], 16;" :: "r"(dst), "l"(src));
}
#define CP_COMMIT() asm volatile("cp.async.commit_group;")
#define CP_WAIT0()  asm volatile("cp.async.wait_group 0;")

__device__ __forceinline__ void ldsm4(unsigned r[4], unsigned addr) {
    asm volatile("ldmatrix.sync.aligned.m8n8.x4.shared.b16 {%0,%1,%2,%3}, [%4];"
                 : "=r"(r[0]), "=r"(r[1]), "=r"(r[2]), "=r"(r[3]) : "r"(addr));
}
__device__ __forceinline__ void mma16816(float c[4], const unsigned a[4], unsigned b0, unsigned b1) {
    asm volatile("mma.sync.aligned.m16n8k16.row.col.f32.bf16.bf16.f32 "
                 "{%0,%1,%2,%3},{%4,%5,%6,%7},{%8,%9},{%0,%1,%2,%3};"
                 : "+f"(c[0]), "+f"(c[1]), "+f"(c[2]), "+f"(c[3])
                 : "r"(a[0]), "r"(a[1]), "r"(a[2]), "r"(a[3]), "r"(b0), "r"(b1));
}
__device__ __forceinline__ unsigned pack_bf2(float a, float b) {
    __nv_bfloat162 h = __floats2bfloat162_rn(a, b);
    return *reinterpret_cast<unsigned*>(&h);
}
// exact sequential-FMA dot over d=0..255 (bit-matches round-1 pipeline)
__device__ __forceinline__ float exact_dist(int n, int k, const float* __restrict__ emb) {
    const float4* xp = (const float4*)(g_xf + (size_t)n * DD);
    const float4* ep = (const float4*)(emb + (size_t)k * DD);
    float dot = 0.f;
#pragma unroll 8
    for (int i = 0; i < 64; i++) {
        float4 xv = xp[i], ev = ep[i];
        dot = __fmaf_rn(xv.x, ev.x, dot);
        dot = __fmaf_rn(xv.y, ev.y, dot);
        dot = __fmaf_rn(xv.z, ev.z, dot);
        dot = __fmaf_rn(xv.w, ev.w, dot);
    }
    return __fsub_rn(__fadd_rn(g_t1[n], g_e2[k]), __fmul_rn(2.0f, dot));
}

// ---------------- prep kernels ----------------
__global__ void prep_e2(const float* __restrict__ emb) {
    int k = blockIdx.x * 8 + (threadIdx.x >> 5);
    int lane = threadIdx.x & 31;
    const float* row = emb + (size_t)k * DD;
    float s = 0.f;
#pragma unroll
    for (int j = 0; j < 8; j++) { float v = row[lane + 32 * j]; s = __fmaf_rn(v, v, s); }
#pragma unroll
    for (int o = 16; o > 0; o >>= 1) s += __shfl_xor_sync(0xffffffffu, s, o);
    if (lane == 0) g_e2[k] = s;
    if (blockIdx.x == 0 && threadIdx.x == 0) g_loss = 0.0;
}

__global__ void prep_t1(const float* __restrict__ ze) {
    int n = blockIdx.x * 256 + threadIdx.x;
    int b = n >> 10, t = n & 1023;
    const float* p = ze + ((size_t)b * DD) * TT + t;
    float acc = 0.f;
    for (int d = 0; d < DD; d++) {
        float v = p[(size_t)d * TT];
        acc = __fadd_rn(acc, __fmul_rn(v, v));
    }
    g_t1[n] = acc;
}

__global__ void prep_ebf(const float* __restrict__ emb) {
    int i = blockIdx.x * 256 + threadIdx.x;   // float4 index
    float4 v = ((const float4*)emb)[i];
    uint2 o;
    o.x = pack_bf2(v.x, v.y);
    o.y = pack_bf2(v.z, v.w);
    ((uint2*)g_ebf)[i] = o;
}

// transpose z_e [b][d][t] -> g_xf/g_xbf row-major [n][d]
__global__ void prep_x(const float* __restrict__ ze) {
    __shared__ float sm[32 * 257];
    int n0 = blockIdx.x * 32;
    int b = n0 >> 10, t0 = n0 & 1023;
    int tid = threadIdx.x, w = tid >> 5, l = tid & 31;
#pragma unroll
    for (int j = 0; j < 32; j++) {
        int d = w * 32 + j;
        sm[l * 257 + d] = ze[((size_t)b * DD + d) * TT + t0 + l];
    }
    __syncthreads();
    int r = tid >> 3, c = tid & 7;
    float4* xo = (float4*)(g_xf + (size_t)(n0 + r) * DD);
    uint2*  bo = (uint2*)(g_xbf + (size_t)(n0 + r) * DD);
#pragma unroll
    for (int j = 0; j < 8; j++) {
        int ch = c + j * 8;
        float4 v;
        v.x = sm[r * 257 + ch * 4 + 0];
        v.y = sm[r * 257 + ch * 4 + 1];
        v.z = sm[r * 257 + ch * 4 + 2];
        v.w = sm[r * 257 + ch * 4 + 3];
        xo[ch] = v;
        uint2 o; o.x = pack_bf2(v.x, v.y); o.y = pack_bf2(v.z, v.w);
        bo[ch] = o;
    }
}

// ---------------- main MMA scan ----------------
#define AS_BYTES 65536
#define ES_BYTES 65536
extern __shared__ unsigned char smem_mma[];

__global__ __launch_bounds__(256, 1) void vq_mma() {
    __shared__ int runmin_s[128];
    __shared__ int cnt_s[128];
    const int tid = threadIdx.x, wid = tid >> 5, lane = tid & 31;
    const int wm = wid & 3, wn = wid >> 2;
    const int n0 = blockIdx.x * 128;

    unsigned As = smem_u32(smem_mma);
    unsigned Es0 = As + AS_BYTES;

    if (tid < 128) { runmin_s[tid] = 0x7F800000; cnt_s[tid] = 0; }

#pragma unroll
    for (int t = 0; t < 16; t++) {
        int i = tid + t * 256;
        int row = i >> 5, p = i & 31;
        cp16(As + row * 512 + ((p ^ (row & 7)) << 4),
             g_xbf + (size_t)(n0 + row) * DD + p * 8);
    }
#pragma unroll
    for (int t = 0; t < 16; t++) {
        int i = tid + t * 256;
        int row = i >> 5, p = i & 31;
        cp16(Es0 + row * 512 + ((p ^ (row & 7)) << 4),
             g_ebf + (size_t)row * DD + p * 8);
    }
    CP_COMMIT();
    CP_WAIT0();
    __syncthreads();

    const int g = lane >> 2;
    float t1v[2][2];
#pragma unroll
    for (int mf = 0; mf < 2; mf++) {
        t1v[mf][0] = g_t1[n0 + wm * 32 + mf * 16 + g];
        t1v[mf][1] = g_t1[n0 + wm * 32 + mf * 16 + g + 8];
    }

    int rowA[2], rowB[4];
#pragma unroll
    for (int mf = 0; mf < 2; mf++) rowA[mf] = wm * 32 + mf * 16 + (lane & 15);
    {
        int q = lane >> 3;
#pragma unroll
        for (int nf2 = 0; nf2 < 4; nf2++)
            rowB[nf2] = wn * 64 + nf2 * 16 + ((q >> 1) << 3) + (lane & 7);
    }
    const int pA = (lane >> 4);
    const int pB = (lane >> 3) & 1;

    int buf = 0;
    for (int kt_i = 0; kt_i < 64; kt_i++) {
        unsigned EsC = Es0 + buf * ES_BYTES;
        if (kt_i + 1 < 64) {
            unsigned EsN = Es0 + (buf ^ 1) * ES_BYTES;
            const unsigned short* src = g_ebf + (size_t)(kt_i + 1) * 128 * DD;
#pragma unroll
            for (int t = 0; t < 16; t++) {
                int i = tid + t * 256;
                int row = i >> 5, p = i & 31;
                cp16(EsN + row * 512 + ((p ^ (row & 7)) << 4), src + (size_t)row * DD + p * 8);
            }
            CP_COMMIT();
        }

        float acc[2][8][4];
#pragma unroll
        for (int mf = 0; mf < 2; mf++)
#pragma unroll
            for (int nf = 0; nf < 8; nf++)
#pragma unroll
                for (int r = 0; r < 4; r++) acc[mf][nf][r] = 0.f;

#pragma unroll
        for (int ks = 0; ks < 16; ks++) {
            unsigned aF[2][4], bF[4][4];
#pragma unroll
            for (int mf = 0; mf < 2; mf++) {
                int row = rowA[mf], p = 2 * ks + pA;
                ldsm4(aF[mf], As + row * 512 + ((p ^ (row & 7)) << 4));
            }
#pragma unroll
            for (int nf2 = 0; nf2 < 4; nf2++) {
                int row = rowB[nf2], p = 2 * ks + pB;
                ldsm4(bF[nf2], EsC + row * 512 + ((p ^ (row & 7)) << 4));
            }
#pragma unroll
            for (int mf = 0; mf < 2; mf++)
#pragma unroll
                for (int nf = 0; nf < 8; nf++)
                    mma16816(acc[mf][nf], aF[mf], bF[nf >> 1][(nf & 1) * 2], bF[nf >> 1][(nf & 1) * 2 + 1]);
        }

        // ===== two-phase epilogue (race-safe candidate collection) =====
        int kt = kt_i * 128;
        int kb0 = kt + wn * 64 + 2 * (lane & 3);

        // phase A: fold this thread's 64 scores into 4 per-row minima, atomicMin to smem
        {
            float lmin[2][2];
            lmin[0][0] = lmin[0][1] = lmin[1][0] = lmin[1][1] = CUDART_INF_F;
#pragma unroll
            for (int nf = 0; nf < 8; nf++) {
                int kb = kb0 + nf * 8;
                float e2a = g_e2[kb], e2b = g_e2[kb + 1];
#pragma unroll
                for (int mf = 0; mf < 2; mf++)
#pragma unroll
                    for (int rg = 0; rg < 4; rg++) {
                        float e2v = (rg & 1) ? e2b : e2a;
                        float s = __fsub_rn(__fadd_rn(t1v[mf][rg >> 1], e2v),
                                            __fmul_rn(2.0f, acc[mf][nf][rg]));
                        if (s < lmin[mf][rg >> 1]) lmin[mf][rg >> 1] = s;
                    }
            }
#pragma unroll
            for (int mf = 0; mf < 2; mf++)
#pragma unroll
                for (int rh = 0; rh < 2; rh++) {
                    int r = wm * 32 + mf * 16 + g + rh * 8;
                    atomicMin(&runmin_s[r], __float_as_int(lmin[mf][rh]));
                }
        }
        __syncthreads();

        // phase B: append with settled thresholds
        {
            float thr[2][2];
#pragma unroll
            for (int mf = 0; mf < 2; mf++)
#pragma unroll
                for (int rh = 0; rh < 2; rh++)
                    thr[mf][rh] = __int_as_float(runmin_s[wm * 32 + mf * 16 + g + rh * 8]) + MARGIN;
#pragma unroll
            for (int nf = 0; nf < 8; nf++) {
                int kb = kb0 + nf * 8;
                float e2a = g_e2[kb], e2b = g_e2[kb + 1];
#pragma unroll
                for (int mf = 0; mf < 2; mf++)
#pragma unroll
                    for (int rg = 0; rg < 4; rg++) {
                        float e2v = (rg & 1) ? e2b : e2a;
                        float s = __fsub_rn(__fadd_rn(t1v[mf][rg >> 1], e2v),
                                            __fmul_rn(2.0f, acc[mf][nf][rg]));
                        if (s <= thr[mf][rg >> 1]) {
                            int r = wm * 32 + mf * 16 + g + ((rg >> 1) << 3);
                            int k = kb + (rg & 1);
                            int pos = atomicAdd(&cnt_s[r], 1);
                            if (pos < CAP)
                                g_cand[(size_t)(n0 + r) * CAP + pos] =
                                    ((unsigned long long)(unsigned)__float_as_int(s) << 32) | (unsigned)k;
                        }
                    }
            }
        }

        CP_WAIT0();
        __syncthreads();
        buf ^= 1;
    }

    if (tid < 128) {
        g_runbits[n0 + tid] = runmin_s[tid];
        g_ccnt[n0 + tid] = cnt_s[tid];
    }
}

// ---------------- exact refine ----------------
__global__ void vq_refine(const float* __restrict__ emb, float* __restrict__ out) {
    int n = blockIdx.x * 256 + threadIdx.x;
    int cnt = g_ccnt[n];
    float bestv = CUDART_INF_F;
    int bestk = 0;
    if (cnt <= CAP) {
        float thr = __int_as_float(g_runbits[n]) + MARGIN;
        const unsigned long long* cl = g_cand + (size_t)n * CAP;
        for (int i = 0; i < cnt; i++) {
            unsigned long long c = cl[i];
            float s = __int_as_float((int)(c >> 32));
            if (s <= thr) {
                int k = (int)(c & 0xffffffffu);
                float dv = exact_dist(n, k, emb);
                if (dv < bestv || (dv == bestv && k < bestk)) { bestv = dv; bestk = k; }
            }
        }
    } else {
        for (int k = 0; k < KK; k++) {   // safety fallback, should never trigger now
            float dv = exact_dist(n, k, emb);
            if (dv < bestv || (dv == bestv && k < bestk)) { bestv = dv; bestk = k; }
        }
    }
    g_idx[n] = bestk;
    out[ZQ_ELEMS + 1 + n] = (float)bestk;
}

// ---------------- gather + STE + loss ----------------
__global__ void vq_gather(const float* __restrict__ ze, const float* __restrict__ emb,
                          float* __restrict__ out) {
    __shared__ float sm[32 * 257];
    __shared__ double sred[256];
    int n0 = blockIdx.x * 32;
    int b = n0 >> 10, t0 = n0 & 1023;
    int tid = threadIdx.x;
    {
        int r = tid >> 3, c = tid & 7;
        int k = g_idx[n0 + r];
        const float4* er = (const float4*)(emb + (size_t)k * DD);
#pragma unroll
        for (int j = 0; j < 8; j++) {
            int ch = c + j * 8;
            float4 v = er[ch];
            sm[r * 257 + ch * 4 + 0] = v.x;
            sm[r * 257 + ch * 4 + 1] = v.y;
            sm[r * 257 + ch * 4 + 2] = v.z;
            sm[r * 257 + ch * 4 + 3] = v.w;
        }
    }
    __syncthreads();
    int w = tid >> 5, l = tid & 31;
    double lsum = 0.0;
#pragma unroll
    for (int j = 0; j < 32; j++) {
        int d = w * 32 + j;
        size_t off = ((size_t)b * DD + d) * TT + t0 + l;
        float e = sm[l * 257 + d];
        float v = ze[off];
        float diff = __fsub_rn(e, v);
        out[off] = __fadd_rn(v, diff);
        lsum += (double)__fmul_rn(diff, diff);
    }
    sred[tid] = lsum;
    __syncthreads();
    for (int s = 128; s > 0; s >>= 1) {
        if (tid < s) sred[tid] += sred[tid + s];
        __syncthreads();
    }
    if (tid == 0) atomicAdd(&g_loss, sred[0]);
}

__global__ void vq_finalize(float* __restrict__ out) {
    out[ZQ_ELEMS] = (float)(g_loss / (double)ZQ_ELEMS);
}

// ---------------- launch ----------------
extern "C" void kernel_launch(void* const* d_in, const int* in_sizes, int n_in,
                              void* d_out, int out_size) {
    (void)in_sizes; (void)n_in; (void)out_size;
    const float* ze = (const float*)d_in[0];
    const float* emb = (const float*)d_in[1];
    float* out = (float*)d_out;

    cudaFuncSetAttribute(vq_mma, cudaFuncAttributeMaxDynamicSharedMemorySize,
                         AS_BYTES + 2 * ES_BYTES);

    prep_e2<<<KK / 8, 256>>>(emb);
    prep_t1<<<NN / 256, 256>>>(ze);
    prep_ebf<<<(KK * DD / 4) / 256, 256>>>(emb);
    prep_x<<<NN / 32, 256>>>(ze);
    vq_mma<<<256, 256, AS_BYTES + 2 * ES_BYTES>>>();
    vq_refine<<<NN / 256, 256>>>(emb, out);
    vq_gather<<<NN / 32, 256>>>(ze, emb, out);
    vq_finalize<<<1, 1>>>(out);
}